// round 11
// baseline (speedup 1.0000x reference)
#include <cuda_runtime.h>
#include <cuda_fp16.h>
#include <cstdint>

#define DDIM 64
#define KCODES 1024
#define NTOK 131072
#define TM 128
#define NTHREADS 512
#define PASSES 4
#define CPASS 256
#define CAP 8
#define MARGIN 0.15f

// ---------------- smem layout (bytes) ----------------
#define OFF_XF    0        // f32 [128][65]  = 33280 (exact, for xn + rescore)
#define OFF_XH    33280    // u32 [64][128]  = 32768 (half2 {x,x} replicated)
#define OFF_CS    66048    // u32 [64][128]  = 32768 (half2 code pairs, per pass)
#define OFF_CN    98816    // f32 [1024]     = 4096
#define OFF_CAND  102912   // u16 [16][128][8] = 32768
#define OFF_REDV  135680   // f32 [16][128]  = 8192
#define OFF_GB    143872   // f32 [128]      = 512
#define OFF_RV2   144384   // f32 [4][128]   = 2048
#define OFF_RI2   146432   // int [4][128]   = 2048
#define OFF_XNS   148480   // f32 [128]
#define OFF_WIX   148992   // int [128]
#define OFF_SCNT  149504   // u8  [16][128]  = 2048 (255 = overflow)
#define SMEM_BYTES 151552

__device__ float g_cn[KCODES];                    // ||c||^2, sequential order (bit-matches ref)
__device__ __align__(16) uint32_t g_ch[DDIM * (KCODES / 2)];  // half2 {c_2j,c_2j+1} [d][j]

__global__ void vq_prep(const float* __restrict__ cb) {
    int k = blockIdx.x * blockDim.x + threadIdx.x;   // 0..1023
    if (k >= KCODES) return;
    const float* cr = cb + k * DDIM;
    float acc = 0.f;
#pragma unroll
    for (int d = 0; d < DDIM; d++) acc = __fadd_rn(acc, __fmul_rn(cr[d], cr[d]));
    g_cn[k] = acc;
    if (k < KCODES / 2) {                             // k = pair index j
        const float* c0 = cb + (2 * k) * DDIM;
        const float* c1 = cb + (2 * k + 1) * DDIM;
#pragma unroll
        for (int d = 0; d < DDIM; d++) {
            __half2 p = __floats2half2_rn(c0[d], c1[d]);
            g_ch[d * (KCODES / 2) + k] = *(uint32_t*)&p;
        }
    }
}

__device__ __forceinline__ uint32_t smem_u32(const void* p) {
    uint32_t a;
    asm("{ .reg .u64 t; cvta.to.shared.u64 t, %1; cvt.u32.u64 %0, t; }" : "=r"(a) : "l"(p));
    return a;
}
__device__ __forceinline__ uint4 lds128(uint32_t a) {
    uint4 v;
    asm volatile("ld.shared.v4.u32 {%0,%1,%2,%3}, [%4];"
                 : "=r"(v.x), "=r"(v.y), "=r"(v.z), "=r"(v.w) : "r"(a));
    return v;
}
__device__ __forceinline__ __half2 u2h(uint32_t u) { return *(__half2*)&u; }

// exact rescore: bit-matches reference (verified R2/R4-R10)
__device__ __forceinline__ float exact_d2(const float* __restrict__ cb,
                                          const float* __restrict__ xrow,
                                          float xn, float cnk, int k) {
    const float4* cr = (const float4*)(cb + k * DDIM);
    float s = 0.f;
#pragma unroll 4
    for (int i = 0; i < 16; i++) {
        float4 v = cr[i];
        s = __fmaf_rn(xrow[4 * i + 0], v.x, s);
        s = __fmaf_rn(xrow[4 * i + 1], v.y, s);
        s = __fmaf_rn(xrow[4 * i + 2], v.z, s);
        s = __fmaf_rn(xrow[4 * i + 3], v.w, s);
    }
    return __fadd_rn(__fsub_rn(xn, __fmul_rn(2.0f, s)), cnk);
}

__device__ __forceinline__ void lex_scan_slice(const float* cb, const float* Cn,
                                               const float* xrow, float xn, int w,
                                               float& bv, int& bi) {
#pragma unroll 1
    for (int p = 0; p < PASSES; p++)
#pragma unroll 1
        for (int j = 0; j < 16; j++) {
            int k = p * CPASS + w * 16 + j;
            float d2 = exact_d2(cb, xrow, xn, Cn[k], k);
            if (d2 < bv || (d2 == bv && k < bi)) { bv = d2; bi = k; }
        }
}

__global__ __launch_bounds__(NTHREADS, 1)
void vq_main(const float* __restrict__ h, const float* __restrict__ cb,
             float* __restrict__ outZ, float* __restrict__ outQ) {
    extern __shared__ char smem[];
    float*    Xf   = (float*)(smem + OFF_XF);
    uint32_t* Xh   = (uint32_t*)(smem + OFF_XH);
    uint32_t* Cs   = (uint32_t*)(smem + OFF_CS);
    float*    Cn   = (float*)(smem + OFF_CN);
    uint16_t* cand = (uint16_t*)(smem + OFF_CAND);
    float*    redv = (float*)(smem + OFF_REDV);
    float*    gb   = (float*)(smem + OFF_GB);
    float*    rv2  = (float*)(smem + OFF_RV2);
    int*      ri2  = (int*)(smem + OFF_RI2);
    float*    xns  = (float*)(smem + OFF_XNS);
    int*      wix  = (int*)(smem + OFF_WIX);
    uint8_t*  sCnt = (uint8_t*)(smem + OFF_SCNT);
    const uint32_t sbase = smem_u32(smem);

    const int tid = threadIdx.x;
    const int w = tid >> 5;
    const int l = tid & 31;
    const int n0 = blockIdx.x * TM;
    const int bb_ = n0 >> 12;
    const long base = (long)bb_ * 262144 + (n0 & 4095);

    // ---- Xf [t][65]: coalesced d-major gmem reads ----
    for (int i = tid; i < 64 * 32; i += NTHREADS) {
        int d = i >> 5, t4 = i & 31;
        float4 v = *(const float4*)(h + base + (long)d * 4096 + t4 * 4);
        Xf[(t4 * 4 + 0) * 65 + d] = v.x;
        Xf[(t4 * 4 + 1) * 65 + d] = v.y;
        Xf[(t4 * 4 + 2) * 65 + d] = v.z;
        Xf[(t4 * 4 + 3) * 65 + d] = v.w;
    }
    for (int i = tid; i < KCODES; i += NTHREADS) Cn[i] = g_cn[i];
    // pass-0 code tile (half2 pairs): Cs[d][j] for j = 0..127
    for (int i = tid; i < 64 * 128 / 4; i += NTHREADS)
        *(uint4*)&Cs[i * 4] = *(const uint4*)&g_ch[(i >> 5) * 512 + ((i & 31) << 2)];
    __syncthreads();

    // ---- exact xn (sequential mul-then-add; reference order) ----
    if (tid < 128) {
        float acc = 0.f;
#pragma unroll
        for (int d = 0; d < 64; d++) {
            float xv = Xf[tid * 65 + d];
            acc = __fadd_rn(acc, __fmul_rn(xv, xv));
        }
        xns[tid] = acc;
    }
    // Xh: replicated half2 {x,x}, [d][t]
    for (int i = tid; i < 64 * 128; i += NTHREADS) {
        int d = i >> 7, t = i & 127;
        __half hx = __float2half_rn(Xf[t * 65 + d]);
        __half2 p = __halves2half2(hx, hx);
        Xh[d * 128 + t] = *(uint32_t*)&p;
    }
    __syncthreads();

    float xnr[4];
    {
        float4 v = *(const float4*)&xns[4 * l];
        xnr[0] = v.x; xnr[1] = v.y; xnr[2] = v.z; xnr[3] = v.w;
    }
    float best[4] = {3.4e38f, 3.4e38f, 3.4e38f, 3.4e38f};
    int cnt[4] = {0, 0, 0, 0};

    const uint32_t xaddr = sbase + OFF_XH + 16u * l;   // this thread's 4 tokens
    const uint32_t caddr = sbase + OFF_CS + 32u * w;   // this warp's 8 code pairs

#pragma unroll 1
    for (int p = 0; p < PASSES; p++) {
        __half2 acc[8][4];
#pragma unroll
        for (int j = 0; j < 8; j++)
#pragma unroll
            for (int t = 0; t < 4; t++) acc[j][t] = __halves2half2(__ushort_as_half(0), __ushort_as_half(0));

#pragma unroll 2
        for (int d = 0; d < 64; d++) {
            uint4 xv = lds128(xaddr + (uint32_t)(d * 512));
            __half2 x0 = u2h(xv.x), x1 = u2h(xv.y), x2 = u2h(xv.z), x3 = u2h(xv.w);
            uint32_t ca = caddr + (uint32_t)(d * 512);
            uint4 c0 = lds128(ca);        // pairs j=0..3 (warp-uniform broadcast)
            uint4 c1 = lds128(ca + 16);   // pairs j=4..7
            __half2 cj;
            cj = u2h(c0.x);
            acc[0][0] = __hfma2(x0, cj, acc[0][0]); acc[0][1] = __hfma2(x1, cj, acc[0][1]);
            acc[0][2] = __hfma2(x2, cj, acc[0][2]); acc[0][3] = __hfma2(x3, cj, acc[0][3]);
            cj = u2h(c0.y);
            acc[1][0] = __hfma2(x0, cj, acc[1][0]); acc[1][1] = __hfma2(x1, cj, acc[1][1]);
            acc[1][2] = __hfma2(x2, cj, acc[1][2]); acc[1][3] = __hfma2(x3, cj, acc[1][3]);
            cj = u2h(c0.z);
            acc[2][0] = __hfma2(x0, cj, acc[2][0]); acc[2][1] = __hfma2(x1, cj, acc[2][1]);
            acc[2][2] = __hfma2(x2, cj, acc[2][2]); acc[2][3] = __hfma2(x3, cj, acc[2][3]);
            cj = u2h(c0.w);
            acc[3][0] = __hfma2(x0, cj, acc[3][0]); acc[3][1] = __hfma2(x1, cj, acc[3][1]);
            acc[3][2] = __hfma2(x2, cj, acc[3][2]); acc[3][3] = __hfma2(x3, cj, acc[3][3]);
            cj = u2h(c1.x);
            acc[4][0] = __hfma2(x0, cj, acc[4][0]); acc[4][1] = __hfma2(x1, cj, acc[4][1]);
            acc[4][2] = __hfma2(x2, cj, acc[4][2]); acc[4][3] = __hfma2(x3, cj, acc[4][3]);
            cj = u2h(c1.y);
            acc[5][0] = __hfma2(x0, cj, acc[5][0]); acc[5][1] = __hfma2(x1, cj, acc[5][1]);
            acc[5][2] = __hfma2(x2, cj, acc[5][2]); acc[5][3] = __hfma2(x3, cj, acc[5][3]);
            cj = u2h(c1.z);
            acc[6][0] = __hfma2(x0, cj, acc[6][0]); acc[6][1] = __hfma2(x1, cj, acc[6][1]);
            acc[6][2] = __hfma2(x2, cj, acc[6][2]); acc[6][3] = __hfma2(x3, cj, acc[6][3]);
            cj = u2h(c1.w);
            acc[7][0] = __hfma2(x0, cj, acc[7][0]); acc[7][1] = __hfma2(x1, cj, acc[7][1]);
            acc[7][2] = __hfma2(x2, cj, acc[7][2]); acc[7][3] = __hfma2(x3, cj, acc[7][3]);
        }

        // epilogue: approx d2 from fp16 s, candidate collection
        const int kw = p * CPASS + w * 16;
#pragma unroll
        for (int j = 0; j < 8; j++) {
            int k0 = kw + 2 * j;
            float cn0 = Cn[k0], cn1 = Cn[k0 + 1];
#pragma unroll
            for (int t = 0; t < 4; t++) {
                float2 s2 = __half22float2(acc[j][t]);
                float d2a = xnr[t] - 2.0f * s2.x + cn0;
                float d2b = xnr[t] - 2.0f * s2.y + cn1;
                if (fminf(d2a, d2b) < best[t] + MARGIN) {
                    int tok = 4 * l + t;
                    int slot = (w * 128 + tok) * CAP;
                    if (d2a < best[t] + MARGIN) {
                        if (cnt[t] < CAP) cand[slot + cnt[t]] = (uint16_t)k0;
                        cnt[t]++;
                    }
                    if (d2b < best[t] + MARGIN) {
                        if (cnt[t] < CAP) cand[slot + cnt[t]] = (uint16_t)(k0 + 1);
                        cnt[t]++;
                    }
                    best[t] = fminf(best[t], fminf(d2a, d2b));
                }
            }
        }

        // share best across warps; reload Cs for next pass
        *(float4*)&redv[w * 128 + 4 * l] = make_float4(best[0], best[1], best[2], best[3]);
        __syncthreads();
        if (tid < 128) {
            float m = redv[tid];
#pragma unroll
            for (int ww = 1; ww < 16; ww++) m = fminf(m, redv[ww * 128 + tid]);
            gb[tid] = m;
        }
        if (p + 1 < PASSES) {
            for (int i = tid; i < 64 * 128 / 4; i += NTHREADS)
                *(uint4*)&Cs[i * 4] =
                    *(const uint4*)&g_ch[(i >> 5) * 512 + (p + 1) * 128 + ((i & 31) << 2)];
        }
        __syncthreads();
        {
            float4 gv = *(const float4*)&gb[4 * l];
            best[0] = fminf(best[0], gv.x); best[1] = fminf(best[1], gv.y);
            best[2] = fminf(best[2], gv.z); best[3] = fminf(best[3], gv.w);
        }
    }

#pragma unroll
    for (int t = 0; t < 4; t++)
        sCnt[w * 128 + 4 * l + t] = (uint8_t)(cnt[t] > CAP ? 255 : cnt[t]);
    __syncthreads();

    // ---- exact rescore: 4 threads per token, each covers 4 warps' lists (R10-verified) ----
    {
        const int t = tid & 127;
        const int p4 = tid >> 7;
        const float* xrow = &Xf[t * 65];
        const float xn = xns[t];
        float bv = 3.4e38f;
        int bi = 0x7fffffff;
        for (int ww = p4 * 4; ww < p4 * 4 + 4; ww++) {
            int n = sCnt[ww * 128 + t];
            if (n == 255) {
                lex_scan_slice(cb, Cn, xrow, xn, ww, bv, bi);
            } else {
                for (int i = 0; i < n; i++) {
                    int k = cand[(ww * 128 + t) * CAP + i];
                    float d2 = exact_d2(cb, xrow, xn, Cn[k], k);
                    if (d2 < bv || (d2 == bv && k < bi)) { bv = d2; bi = k; }
                }
            }
        }
        rv2[p4 * 128 + t] = bv;
        ri2[p4 * 128 + t] = bi;
    }
    __syncthreads();

    if (tid < 128) {
        float bv = rv2[tid];
        int bi = ri2[tid];
#pragma unroll
        for (int p4 = 1; p4 < 4; p4++) {
            float v = rv2[p4 * 128 + tid];
            int i2 = ri2[p4 * 128 + tid];
            if (v < bv || (v == bv && i2 < bi)) { bv = v; bi = i2; }
        }
        wix[tid] = bi;
        if (outZ) outZ[n0 + tid] = (float)bi;
    }
    __syncthreads();

    // ---- q gather ----
    if (outQ) {
        for (int i = tid; i < 128 * 16; i += NTHREADS) {
            int tt = i >> 4, c4 = i & 15;
            float4 v = *(const float4*)&cb[wix[tt] * DDIM + c4 * 4];
            *(float4*)&outQ[(long)(n0 + tt) * DDIM + c4 * 4] = v;
        }
    }
}

extern "C" void kernel_launch(void* const* d_in, const int* in_sizes, int n_in,
                              void* d_out, int out_size) {
    const float* h = (const float*)d_in[0];
    const float* cb = (const float*)d_in[1];
    float* out = (float*)d_out;

    float* outZ = nullptr;
    float* outQ = nullptr;
    if (out_size >= NTOK + NTOK * DDIM) { outZ = out; outQ = out + NTOK; }
    else if (out_size == NTOK * DDIM)   { outQ = out; }
    else                                { outZ = out; }

    cudaFuncSetAttribute(vq_main, cudaFuncAttributeMaxDynamicSharedMemorySize, SMEM_BYTES);
    vq_prep<<<4, 256>>>(cb);
    vq_main<<<NTOK / TM, NTHREADS, SMEM_BYTES>>>(h, cb, outZ, outQ);
}